// round 15
// baseline (speedup 1.0000x reference)
#include <cuda_runtime.h>
#include <cuda_bf16.h>
#include <math.h>
#include <stdint.h>

#define NB    2048
#define NBITS 64
#define NH    512
#define NHV   256

typedef unsigned long long ull;

__device__ float g_sp[NB * NH];
__device__ float g_vs[NB * NHV];
__device__ uint8_t g_w2f8[NH * NH];     // W2^T e4m3 (x16)  [n][k]
__device__ uint8_t g_w3f8[NBITS * NH];  // W3^T e4m3 (x16)  [n3][k]
__device__ int g_sync[257];             // [0]=prep count, [1+i]=shift block i done

__device__ __forceinline__ uint32_t smem_u32(const void* p) {
    uint32_t a;
    asm("{ .reg .u64 t; cvta.to.shared.u64 t, %1; cvt.u32.u64 %0, t; }"
        : "=r"(a) : "l"(p));
    return a;
}
__device__ __forceinline__ uint16_t pack_e4m3x2(float lo, float hi) {
    uint16_t r;
    asm("cvt.rn.satfinite.e4m3x2.f32 %0, %1, %2;" : "=h"(r) : "f"(hi), "f"(lo));
    return r;
}
__device__ __forceinline__ uint32_t pack_e4m3x4(float a, float b, float c, float d) {
    uint16_t lo = pack_e4m3x2(a, b);
    uint16_t hi = pack_e4m3x2(c, d);
    uint32_t r;
    asm("mov.b32 %0, {%1, %2};" : "=r"(r) : "h"(lo), "h"(hi));
    return r;
}
__device__ __forceinline__ void cp16(uint32_t dst, const void* src) {
    asm volatile("cp.async.cg.shared.global [%0], [%1], 16;"
                 :: "r"(dst), "l"(src) : "memory");
}
__device__ __forceinline__ void mma_fp8(float* c, const uint32_t* a,
                                        uint32_t b0, uint32_t b1) {
    asm volatile("mma.sync.aligned.m16n8k32.row.col.f32.e4m3.e4m3.f32 "
                 "{%0,%1,%2,%3}, {%4,%5,%6,%7}, {%8,%9}, {%0,%1,%2,%3};"
                 : "+f"(c[0]), "+f"(c[1]), "+f"(c[2]), "+f"(c[3])
                 : "r"(a[0]), "r"(a[1]), "r"(a[2]), "r"(a[3]),
                   "r"(b0), "r"(b1));
}
__device__ __forceinline__ void ldm_x4(uint32_t* r, uint32_t addr) {
    asm volatile("ldmatrix.sync.aligned.m8n8.x4.shared.b16 {%0,%1,%2,%3}, [%4];"
                 : "=r"(r[0]), "=r"(r[1]), "=r"(r[2]), "=r"(r[3]) : "r"(addr));
}
__device__ __forceinline__ void ffma2(ull& c, ull a, ull b) {
    asm("fma.rn.f32x2 %0, %1, %2, %0;" : "+l"(c) : "l"(a), "l"(b));
}
__device__ __forceinline__ ull dupf(float x) {
    ull r; asm("mov.b64 %0, {%1, %1};" : "=l"(r) : "f"(x)); return r;
}
__device__ __forceinline__ ull packf2(float x, float y) {
    ull r; asm("mov.b64 %0, {%1, %2};" : "=l"(r) : "f"(x), "f"(y)); return r;
}
__device__ __forceinline__ float2 unpf2(ull v) {
    float2 r; asm("mov.b64 {%0, %1}, %2;" : "=f"(r.x), "=f"(r.y) : "l"(v)); return r;
}

#define SCALE     16.0f
#define INV_SC2   (1.0f / 256.0f)

// SMEM layout (fp8, M=64 per CTA, 3 W2 buffers): total 102912 B -> 2 CTAs/SM
#define H1_OFF   0
#define H1_STR   528
#define W2_OFF   33792     // 3 x 18432 = 55296
#define W2_TILE  18432
#define W2_STR   144
#define W3_OFF   89088     // 9216
#define B2_OFF   98304     // 2048
#define B3_OFF   100352
#define AB_OFF   100608
#define VS_OFF   100864
#define VW2_OFF  101888
#define SM_TOTAL 102912
#define LG_OFF   W2_OFF

#define AUX_BLOCKS 544   // 256 shift + 256 W2 prep + 32 W3 prep

__global__ __launch_bounds__(256, 2) void fused_kernel(
    const float* __restrict__ shift_bits,
    const float* __restrict__ sd_w1, const float* __restrict__ sd_b1,
    const float* __restrict__ sd_w2, const float* __restrict__ sd_b2,
    const float* __restrict__ sd_w3, const float* __restrict__ sd_b3,
    const float* __restrict__ ix_w1, const float* __restrict__ v_w1,
    const float* __restrict__ ix_w2, const float* __restrict__ ix_w3,
    const float* __restrict__ a_bits,
    const float* __restrict__ ix_b1, const float* __restrict__ ix_b2,
    const float* __restrict__ ix_b3,
    const float* __restrict__ v_b1,  const float* __restrict__ v_w2,
    const float* __restrict__ v_b2,
    float* __restrict__ out)
{
    extern __shared__ char bp[];
    const int bid = blockIdx.x;
    const int t   = threadIdx.x;

    // =======================================================================
    // AUX: weight prep blocks (256..543)
    // =======================================================================
    if (bid >= 256 && bid < AUX_BLOCKS) {
        if (bid < 512) {                       // W2: transpose + scale + fp8
            int idx = (bid - 256) * 256 + t;
            int n = idx >> 7, k4 = (idx & 127) * 4;
            float w0 = ix_w2[(k4 + 0) * NH + n] * SCALE;
            float w1 = ix_w2[(k4 + 1) * NH + n] * SCALE;
            float w2v = ix_w2[(k4 + 2) * NH + n] * SCALE;
            float w3v = ix_w2[(k4 + 3) * NH + n] * SCALE;
            ((uint32_t*)g_w2f8)[n * 128 + (idx & 127)] = pack_e4m3x4(w0, w1, w2v, w3v);
        } else {                               // W3
            int idx = (bid - 512) * 256 + t;
            int n3 = idx >> 7, k4g = idx & 127;
            int k4 = k4g * 4;
            float w0 = ix_w3[(k4 + 0) * NBITS + n3] * SCALE;
            float w1 = ix_w3[(k4 + 1) * NBITS + n3] * SCALE;
            float w2v = ix_w3[(k4 + 2) * NBITS + n3] * SCALE;
            float w3v = ix_w3[(k4 + 3) * NBITS + n3] * SCALE;
            ((uint32_t*)g_w3f8)[n3 * 128 + k4g] = pack_e4m3x4(w0, w1, w2v, w3v);
        }
        __threadfence();
        __syncthreads();
        if (t == 0) atomicAdd(&g_sync[0], 1);
        return;
    }

    // =======================================================================
    // AUX: shift MLP blocks (0..255), FFMA2 row-pair packed, smem-aliased
    // =======================================================================
    if (bid < 256) {
        ull   (*xs2)[NBITS]  = (ull(*)[NBITS]) (bp + 0);
        ull   (*hs2)[NH]     = (ull(*)[NH])    (bp + 2048);
        ull   (*gs2)[NH]     = (ull(*)[NH])    (bp + 18432);
        float (*lgs)[NBITS]  = (float(*)[NBITS])(bp + 34816);
        float (*sms)[NBITS]  = (float(*)[NBITS])(bp + 36864);
        ull   (*sms2)[NBITS] = (ull(*)[NBITS]) (bp + 38912);

        const int b0 = bid * 8;
        const int c0 = 2 * t;

        {
            int p = t >> 6, k = t & 63;
            xs2[p][k] = packf2(shift_bits[(b0 + p) * NBITS + k],
                               shift_bits[(b0 + p + 4) * NBITS + k]);
        }
        __syncthreads();

        {   // layer 1
            ull a0[4], a1[4];
            #pragma unroll
            for (int p = 0; p < 4; p++) { a0[p] = 0; a1[p] = 0; }
            for (int k = 0; k < NBITS; k++) {
                float2 wv = ((const float2*)(sd_w1 + k * NH))[t];
                ull w0 = dupf(wv.x), w1 = dupf(wv.y);
                #pragma unroll
                for (int p = 0; p < 4; p++) {
                    ull x = xs2[p][k];
                    ffma2(a0[p], x, w0);
                    ffma2(a1[p], x, w1);
                }
            }
            float2 bv = ((const float2*)sd_b1)[t];
            #pragma unroll
            for (int p = 0; p < 4; p++) {
                float2 v0 = unpf2(a0[p]), v1 = unpf2(a1[p]);
                hs2[p][c0]     = packf2(fmaxf(v0.x + bv.x, 0.f), fmaxf(v0.y + bv.x, 0.f));
                hs2[p][c0 + 1] = packf2(fmaxf(v1.x + bv.y, 0.f), fmaxf(v1.y + bv.y, 0.f));
            }
        }
        __syncthreads();

        {   // layer 2
            ull a0[4], a1[4];
            #pragma unroll
            for (int p = 0; p < 4; p++) { a0[p] = 0; a1[p] = 0; }
            for (int k = 0; k < NH; k++) {
                float2 wv = ((const float2*)(sd_w2 + k * NH))[t];
                ull w0 = dupf(wv.x), w1 = dupf(wv.y);
                #pragma unroll
                for (int p = 0; p < 4; p++) {
                    ull h = hs2[p][k];
                    ffma2(a0[p], h, w0);
                    ffma2(a1[p], h, w1);
                }
            }
            float2 bv = ((const float2*)sd_b2)[t];
            #pragma unroll
            for (int p = 0; p < 4; p++) {
                float2 v0 = unpf2(a0[p]), v1 = unpf2(a1[p]);
                gs2[p][c0]     = packf2(fmaxf(v0.x + bv.x, 0.f), fmaxf(v0.y + bv.x, 0.f));
                gs2[p][c0 + 1] = packf2(fmaxf(v1.x + bv.y, 0.f), fmaxf(v1.y + bv.y, 0.f));
            }
        }
        __syncthreads();

        {   // layer 3
            int r = t >> 5, j = t & 31;
            const float* gview = (const float*)gs2;
            int lanesel = r >> 2, pp = r & 3;
            float acc0 = 0.f, acc1 = 0.f;
            for (int k = 0; k < NH; k++) {
                float gv = gview[(pp * NH + k) * 2 + lanesel];
                acc0 = fmaf(gv, sd_w3[k * NBITS + j],      acc0);
                acc1 = fmaf(gv, sd_w3[k * NBITS + j + 32], acc1);
            }
            lgs[r][j]      = acc0 + sd_b3[j];
            lgs[r][j + 32] = acc1 + sd_b3[j + 32];
        }
        __syncthreads();

        {   // softmax
            int wr = t >> 5, l = t & 31;
            float v0 = lgs[wr][l], v1 = lgs[wr][l + 32];
            float m = fmaxf(v0, v1);
            #pragma unroll
            for (int o = 16; o > 0; o >>= 1) m = fmaxf(m, __shfl_xor_sync(0xffffffffu, m, o));
            float e0 = expf(v0 - m), e1 = expf(v1 - m);
            float s = e0 + e1;
            #pragma unroll
            for (int o = 16; o > 0; o >>= 1) s += __shfl_xor_sync(0xffffffffu, s, o);
            float inv = 1.f / s;
            sms[wr][l] = e0 * inv;
            sms[wr][l + 32] = e1 * inv;
        }
        __syncthreads();
        {
            int p = t >> 6, k = t & 63;
            sms2[p][k] = packf2(sms[p][k], sms[p + 4][k]);
        }
        __syncthreads();

        {   // shift_part
            ull a0[4], a1[4];
            #pragma unroll
            for (int p = 0; p < 4; p++) { a0[p] = 0; a1[p] = 0; }
            for (int k = 0; k < NBITS; k++) {
                float2 wv = ((const float2*)(ix_w1 + (NBITS + k) * NH))[t];
                ull w0 = dupf(wv.x), w1 = dupf(wv.y);
                #pragma unroll
                for (int p = 0; p < 4; p++) {
                    ull s = sms2[p][k];
                    ffma2(a0[p], s, w0);
                    ffma2(a1[p], s, w1);
                }
            }
            #pragma unroll
            for (int p = 0; p < 4; p++) {
                float2 v0 = unpf2(a0[p]), v1 = unpf2(a1[p]);
                g_sp[(b0 + p) * NH + c0]         = v0.x;
                g_sp[(b0 + p + 4) * NH + c0]     = v0.y;
                g_sp[(b0 + p) * NH + c0 + 1]     = v1.x;
                g_sp[(b0 + p + 4) * NH + c0 + 1] = v1.y;
            }
        }

        if (t < 128) {   // v_shift
            ull a0[4], a1[4];
            #pragma unroll
            for (int p = 0; p < 4; p++) { a0[p] = 0; a1[p] = 0; }
            for (int k = 0; k < NBITS; k++) {
                float2 wv = ((const float2*)(v_w1 + (NBITS + k) * NHV))[t];
                ull w0 = dupf(wv.x), w1 = dupf(wv.y);
                #pragma unroll
                for (int p = 0; p < 4; p++) {
                    ull s = sms2[p][k];
                    ffma2(a0[p], s, w0);
                    ffma2(a1[p], s, w1);
                }
            }
            #pragma unroll
            for (int p = 0; p < 4; p++) {
                float2 v0 = unpf2(a0[p]), v1 = unpf2(a1[p]);
                g_vs[(b0 + p) * NHV + c0]         = v0.x;
                g_vs[(b0 + p + 4) * NHV + c0]     = v0.y;
                g_vs[(b0 + p) * NHV + c0 + 1]     = v1.x;
                g_vs[(b0 + p + 4) * NHV + c0 + 1] = v1.y;
            }
        }

        __threadfence();
        __syncthreads();
        if (t == 0) atomicExch(&g_sync[1 + bid], 1);
        return;
    }

    // =======================================================================
    // MAIN: FP8 mma chain, batch b = bid - 544, 2 CTAs/SM, 3-buffer pipeline.
    // =======================================================================
    const int b = bid - AUX_BLOCKS;

    float* b2s  = (float*)(bp + B2_OFF);
    float* b3s  = (float*)(bp + B3_OFF);
    float* ab_s = (float*)(bp + AB_OFF);
    float* vs_s = (float*)(bp + VS_OFF);
    float* vw2s = (float*)(bp + VW2_OFF);

    const int lane = t & 31, w = t >> 5;
    const int g = lane >> 2, tg = lane & 3;
    const int mg = w & 1, ng = w >> 1;       // 2m x 4n warp grid
    const uint32_t smb = smem_u32(bp);

    // independent staging (no aux deps)
    for (int i = t; i < NH; i += 256)
        b2s[i] = ix_b2[i] * SCALE;
    vw2s[t] = v_w2[t];
    if (t < NBITS) { b3s[t] = ix_b3[t]; ab_s[t] = a_bits[b * NBITS + t]; }

    // wait for this batch's shift block, then build h1 (overlaps prep wait)
    if (t == 0) {
        volatile int* sy = g_sync;
        while (sy[1 + (b >> 3)] == 0) __nanosleep(100);
    }
    __syncthreads();
    __threadfence();

    vs_s[t] = g_vs[b * NHV + t] + v_b1[t];

    #pragma unroll 4
    for (int i = 0; i < 32; i++) {
        int idx = t + i * 256;
        int mm = idx >> 7, qq = idx & 127;
        int k = qq * 4;
        float4 p  = *(const float4*)(ix_w1 + mm * NH + k);
        float4 s  = *(const float4*)(g_sp + b * NH + k);
        float4 bb = *(const float4*)(ix_b1 + k);
        float v0 = fmaxf(p.x + s.x + bb.x, 0.f) * SCALE;
        float v1 = fmaxf(p.y + s.y + bb.y, 0.f) * SCALE;
        float v2 = fmaxf(p.z + s.z + bb.z, 0.f) * SCALE;
        float v3 = fmaxf(p.w + s.w + bb.w, 0.f) * SCALE;
        *(uint32_t*)(bp + H1_OFF + mm * H1_STR + k) = pack_e4m3x4(v0, v1, v2, v3);
    }

    // wait for weight preps, then start the W2 pipeline (2 chunks ahead)
    if (t == 0) {
        volatile int* sy = g_sync;
        while (sy[0] < 288) __nanosleep(200);
    }
    __syncthreads();
    __threadfence();

    #pragma unroll
    for (int pc = 0; pc < 2; pc++) {   // groups g0, g1 = W2 chunks 0, 1
        const uint8_t* src = g_w2f8 + ((pc >> 2) * 128) * NH + (pc & 3) * 128;
        uint32_t dstb = smb + W2_OFF + pc * W2_TILE;
        #pragma unroll
        for (int i = 0; i < 4; i++) {
            int idx = t + i * 256;
            int row = idx >> 3, c16 = idx & 7;
            cp16(dstb + row * W2_STR + c16 * 16, src + row * NH + c16 * 16);
        }
        asm volatile("cp.async.commit_group;" ::: "memory");
    }

    float lg[2][2][4];
    #pragma unroll
    for (int mt = 0; mt < 2; mt++)
        #pragma unroll
        for (int nt = 0; nt < 2; nt++)
            #pragma unroll
            for (int j2 = 0; j2 < 4; j2++) lg[mt][nt][j2] = 0.f;

    float acc[2][4][4];

    const uint32_t bfrag = (uint32_t)((lane & 7) * W2_STR + (lane >> 3) * 16);
    uint32_t h1a[2];
    h1a[0] = smb + H1_OFF + (uint32_t)((mg * 32 + (lane & 15)) * H1_STR + (lane >> 4) * 16);
    h1a[1] = h1a[0] + 16 * H1_STR;
    const uint32_t w3b = smb + W3_OFF + (uint32_t)(ng * 16 * W2_STR) + bfrag;

    #pragma unroll
    for (int c = 0; c < 16; c++) {
        const int nb = c >> 2, kb = c & 3;
        const int pre = c + 2;
        if (pre < 16) {
            int nnb = pre >> 2, nkb = pre & 3;
            const uint8_t* src = g_w2f8 + (nnb * 128) * NH + nkb * 128;
            uint32_t dstb = smb + W2_OFF + (pre % 3) * W2_TILE;
            #pragma unroll
            for (int i = 0; i < 4; i++) {
                int idx = t + i * 256;
                int row = idx >> 3, c16 = idx & 7;
                cp16(dstb + row * W2_STR + c16 * 16, src + row * NH + c16 * 16);
            }
            if (kb == 0) {   // stage W3 for this nb (used at c+3; ready by c+2)
                #pragma unroll
                for (int i = 0; i < 2; i++) {
                    int idx = t + i * 256;
                    int row = idx >> 3, c16 = idx & 7;
                    cp16(smb + W3_OFF + row * W2_STR + c16 * 16,
                         g_w3f8 + row * NH + nb * 128 + c16 * 16);
                }
            }
            asm volatile("cp.async.commit_group;" ::: "memory");
            asm volatile("cp.async.wait_group 2;" ::: "memory");
        } else if (c == 14) {
            asm volatile("cp.async.wait_group 1;" ::: "memory");
        } else {
            asm volatile("cp.async.wait_group 0;" ::: "memory");
        }
        __syncthreads();

        if (kb == 0) {
            #pragma unroll
            for (int mt = 0; mt < 2; mt++)
                #pragma unroll
                for (int nt = 0; nt < 4; nt++) {
                    acc[mt][nt][0] = 0.f; acc[mt][nt][1] = 0.f;
                    acc[mt][nt][2] = 0.f; acc[mt][nt][3] = 0.f;
                }
        }

        const uint32_t bufA = smb + W2_OFF + (c % 3) * W2_TILE;
        const uint32_t w2b = bufA + (uint32_t)(ng * 32 * W2_STR) + bfrag;
        const uint32_t akb = (uint32_t)(kb * 128);

        #pragma unroll
        for (int ks2 = 0; ks2 < 2; ks2++) {
            uint32_t Bv[4][4];
            #pragma unroll
            for (int nt = 0; nt < 4; nt++)
                ldm_x4(Bv[nt], w2b + nt * (8 * W2_STR) + ks2 * 64);
            uint32_t Am[2][2][4];
            #pragma unroll
            for (int mt = 0; mt < 2; mt++) {
                ldm_x4(Am[mt][0], h1a[mt] + akb + (2 * ks2)     * 32);
                ldm_x4(Am[mt][1], h1a[mt] + akb + (2 * ks2 + 1) * 32);
            }
            #pragma unroll
            for (int mt = 0; mt < 2; mt++)
                #pragma unroll
                for (int nt = 0; nt < 4; nt++) {
                    mma_fp8(acc[mt][nt], Am[mt][0], Bv[nt][0], Bv[nt][1]);
                    mma_fp8(acc[mt][nt], Am[mt][1], Bv[nt][2], Bv[nt][3]);
                }
        }

        if (kb == 3) {
            __syncthreads();   // bufA fully read -> reuse for h2 (e4m3 x16)
            #pragma unroll
            for (int mt = 0; mt < 2; mt++)
                #pragma unroll
                for (int nt = 0; nt < 4; nt++) {
                    int col = ng * 32 + nt * 8 + tg * 2;
                    float bb0 = b2s[nb * 128 + col], bb1 = b2s[nb * 128 + col + 1];
                    int r0 = mg * 32 + mt * 16 + g;
                    uint16_t p0 = pack_e4m3x2(
                        fmaxf(acc[mt][nt][0] * 0.0625f + bb0, 0.f),
                        fmaxf(acc[mt][nt][1] * 0.0625f + bb1, 0.f));
                    uint16_t p1 = pack_e4m3x2(
                        fmaxf(acc[mt][nt][2] * 0.0625f + bb0, 0.f),
                        fmaxf(acc[mt][nt][3] * 0.0625f + bb1, 0.f));
                    *(uint16_t*)(bp + (bufA - smb) + r0 * W2_STR + col) = p0;
                    *(uint16_t*)(bp + (bufA - smb) + (r0 + 8) * W2_STR + col) = p1;
                }
            __syncthreads();

            uint32_t a2b[2];
            a2b[0] = bufA + (uint32_t)((mg * 32 + (lane & 15)) * W2_STR + (lane >> 4) * 16);
            a2b[1] = a2b[0] + 16 * W2_STR;
            #pragma unroll
            for (int ks2 = 0; ks2 < 2; ks2++) {
                uint32_t B2v[2][4];
                #pragma unroll
                for (int nt = 0; nt < 2; nt++)
                    ldm_x4(B2v[nt], w3b + nt * (8 * W2_STR) + ks2 * 64);
                uint32_t A2[2][2][4];
                #pragma unroll
                for (int mt = 0; mt < 2; mt++) {
                    ldm_x4(A2[mt][0], a2b[mt] + (2 * ks2)     * 32);
                    ldm_x4(A2[mt][1], a2b[mt] + (2 * ks2 + 1) * 32);
                }
                #pragma unroll
                for (int mt = 0; mt < 2; mt++)
                    #pragma unroll
                    for (int nt = 0; nt < 2; nt++) {
                        mma_fp8(lg[mt][nt], A2[mt][0], B2v[nt][0], B2v[nt][1]);
                        mma_fp8(lg[mt][nt], A2[mt][1], B2v[nt][2], B2v[nt][3]);
                    }
            }
        }
        __syncthreads();
    }

    // logits -> smem (f32, stride 68), reusing W2 buffer 0
    float* lbuf = (float*)(bp + LG_OFF);
    #pragma unroll
    for (int mt = 0; mt < 2; mt++)
        #pragma unroll
        for (int nt = 0; nt < 2; nt++) {
            int col = ng * 16 + nt * 8 + tg * 2;
            int r0 = mg * 32 + mt * 16 + g;
            lbuf[r0 * 68 + col]     = lg[mt][nt][0];
            lbuf[r0 * 68 + col + 1] = lg[mt][nt][1];
            lbuf[(r0 + 8) * 68 + col]     = lg[mt][nt][2];
            lbuf[(r0 + 8) * 68 + col + 1] = lg[mt][nt][3];
        }
    __syncthreads();

    // epilogue: 4 threads per row (quad), 64 rows. lg = 256 x true logits.
    {
        const int row = t >> 2, tq = t & 3;
        float v[16];
        float mx = -1e30f;
        #pragma unroll
        for (int i = 0; i < 16; i++) {
            int col = i * 4 + tq;
            v[i] = lbuf[row * 68 + col] * INV_SC2 + b3s[col];
            mx = fmaxf(mx, v[i]);
        }
        mx = fmaxf(mx, __shfl_xor_sync(0xffffffffu, mx, 1));
        mx = fmaxf(mx, __shfl_xor_sync(0xffffffffu, mx, 2));

        float den = 0.f, num = 0.f;
        #pragma unroll
        for (int i = 0; i < 16; i++) {
            float e = expf(v[i] - mx);
            den += e;
            num = fmaf(e, ab_s[i * 4 + tq], num);
        }
        den += __shfl_xor_sync(0xffffffffu, den, 1);
        den += __shfl_xor_sync(0xffffffffu, den, 2);
        num += __shfl_xor_sync(0xffffffffu, num, 1);
        num += __shfl_xor_sync(0xffffffffu, num, 2);
        float pointed = num / den;

        const float* vrow = v_w1 + row * NHV;
        float acc2 = 0.f;
        #pragma unroll 8
        for (int jj = 0; jj < 64; jj++) {
            int j = jj * 4 + tq;
            float vh = fmaxf(vrow[j] + vs_s[j], 0.f);
            acc2 = fmaf(vh, vw2s[j], acc2);
        }
        acc2 += __shfl_xor_sync(0xffffffffu, acc2, 1);
        acc2 += __shfl_xor_sync(0xffffffffu, acc2, 2);
        if (tq == 0) {
            float vlog = acc2 + v_b2[0];
            out[b * NBITS + row] = pointed * (1.f / (1.f + expf(-vlog)));
        }
    }
}

extern "C" void kernel_launch(void* const* d_in, const int* in_sizes, int n_in,
                              void* d_out, int out_size)
{
    const float* a_bits     = (const float*)d_in[0];
    const float* shift_bits = (const float*)d_in[1];
    const float* sd_w1 = (const float*)d_in[2];
    const float* sd_b1 = (const float*)d_in[3];
    const float* sd_w2 = (const float*)d_in[4];
    const float* sd_b2 = (const float*)d_in[5];
    const float* sd_w3 = (const float*)d_in[6];
    const float* sd_b3 = (const float*)d_in[7];
    const float* ix_w1 = (const float*)d_in[8];
    const float* ix_b1 = (const float*)d_in[9];
    const float* ix_w2 = (const float*)d_in[10];
    const float* ix_b2 = (const float*)d_in[11];
    const float* ix_w3 = (const float*)d_in[12];
    const float* ix_b3 = (const float*)d_in[13];
    const float* v_w1  = (const float*)d_in[14];
    const float* v_b1  = (const float*)d_in[15];
    const float* v_w2  = (const float*)d_in[16];
    const float* v_b2  = (const float*)d_in[17];
    float* out = (float*)d_out;

    cudaFuncSetAttribute(fused_kernel,
                         cudaFuncAttributeMaxDynamicSharedMemorySize, SM_TOTAL);

    void* sync_ptr = nullptr;
    cudaGetSymbolAddress(&sync_ptr, g_sync);
    cudaMemsetAsync(sync_ptr, 0, sizeof(int) * 257);

    fused_kernel<<<AUX_BLOCKS + NB, 256, SM_TOTAL>>>(
        shift_bits, sd_w1, sd_b1, sd_w2, sd_b2, sd_w3, sd_b3,
        ix_w1, v_w1, ix_w2, ix_w3,
        a_bits, ix_b1, ix_b2, ix_b3, v_b1, v_w2, v_b2, out);
}

// round 16
// speedup vs baseline: 1.0745x; 1.0745x over previous
#include <cuda_runtime.h>
#include <cuda_bf16.h>
#include <math.h>
#include <stdint.h>

#define NB    2048
#define NBITS 64
#define NH    512
#define NHV   256

typedef unsigned long long ull;

__device__ float g_sp[NB * NH];
__device__ float g_vs[NB * NHV];
__device__ uint8_t g_w2f8[NH * NH];     // W2^T e4m3 (x16)  [n][k]
__device__ uint8_t g_w3f8[NBITS * NH];  // W3^T e4m3 (x16)  [n3][k]
__device__ int g_sync[257];             // [0]=prep count, [1+i]=shift block i done

__device__ __forceinline__ uint32_t smem_u32(const void* p) {
    uint32_t a;
    asm("{ .reg .u64 t; cvta.to.shared.u64 t, %1; cvt.u32.u64 %0, t; }"
        : "=r"(a) : "l"(p));
    return a;
}
__device__ __forceinline__ uint16_t pack_e4m3x2(float lo, float hi) {
    uint16_t r;
    asm("cvt.rn.satfinite.e4m3x2.f32 %0, %1, %2;" : "=h"(r) : "f"(hi), "f"(lo));
    return r;
}
__device__ __forceinline__ uint32_t pack_e4m3x4(float a, float b, float c, float d) {
    uint16_t lo = pack_e4m3x2(a, b);
    uint16_t hi = pack_e4m3x2(c, d);
    uint32_t r;
    asm("mov.b32 %0, {%1, %2};" : "=r"(r) : "h"(lo), "h"(hi));
    return r;
}
__device__ __forceinline__ void cp16(uint32_t dst, const void* src) {
    asm volatile("cp.async.cg.shared.global [%0], [%1], 16;"
                 :: "r"(dst), "l"(src) : "memory");
}
__device__ __forceinline__ void mma_fp8(float* c, const uint32_t* a,
                                        uint32_t b0, uint32_t b1) {
    asm volatile("mma.sync.aligned.m16n8k32.row.col.f32.e4m3.e4m3.f32 "
                 "{%0,%1,%2,%3}, {%4,%5,%6,%7}, {%8,%9}, {%0,%1,%2,%3};"
                 : "+f"(c[0]), "+f"(c[1]), "+f"(c[2]), "+f"(c[3])
                 : "r"(a[0]), "r"(a[1]), "r"(a[2]), "r"(a[3]),
                   "r"(b0), "r"(b1));
}
__device__ __forceinline__ void ldm_x4(uint32_t* r, uint32_t addr) {
    asm volatile("ldmatrix.sync.aligned.m8n8.x4.shared.b16 {%0,%1,%2,%3}, [%4];"
                 : "=r"(r[0]), "=r"(r[1]), "=r"(r[2]), "=r"(r[3]) : "r"(addr));
}
__device__ __forceinline__ void ffma2(ull& c, ull a, ull b) {
    asm("fma.rn.f32x2 %0, %1, %2, %0;" : "+l"(c) : "l"(a), "l"(b));
}
__device__ __forceinline__ ull dupf(float x) {
    ull r; asm("mov.b64 %0, {%1, %1};" : "=l"(r) : "f"(x)); return r;
}
__device__ __forceinline__ ull packf2(float x, float y) {
    ull r; asm("mov.b64 %0, {%1, %2};" : "=l"(r) : "f"(x), "f"(y)); return r;
}
__device__ __forceinline__ float2 unpf2(ull v) {
    float2 r; asm("mov.b64 {%0, %1}, %2;" : "=f"(r.x), "=f"(r.y) : "l"(v)); return r;
}

#define SCALE     16.0f
#define INV_SC2   (1.0f / 256.0f)

// SMEM layout (fp8, M=64 per CTA, 2 W2 bufs + dedicated H2): 93696 B -> 2 CTAs/SM
#define H1_OFF   0         // 33792
#define H1_STR   528
#define W2_OFF   33792     // 2 x 18432
#define W2_TILE  18432
#define W2_STR   144
#define W3_OFF   70656     // 9216
#define H2_OFF   79872     // 9216 (64 rows x 144)
#define B2_OFF   89088     // 2048
#define B3_OFF   91136
#define AB_OFF   91392
#define VS_OFF   91648
#define VW2_OFF  92672
#define SM_TOTAL 93696
#define LG_OFF   W2_OFF

#define AUX_BLOCKS 544   // 256 shift + 256 W2 prep + 32 W3 prep

__global__ __launch_bounds__(256, 2) void fused_kernel(
    const float* __restrict__ shift_bits,
    const float* __restrict__ sd_w1, const float* __restrict__ sd_b1,
    const float* __restrict__ sd_w2, const float* __restrict__ sd_b2,
    const float* __restrict__ sd_w3, const float* __restrict__ sd_b3,
    const float* __restrict__ ix_w1, const float* __restrict__ v_w1,
    const float* __restrict__ ix_w2, const float* __restrict__ ix_w3,
    const float* __restrict__ a_bits,
    const float* __restrict__ ix_b1, const float* __restrict__ ix_b2,
    const float* __restrict__ ix_b3,
    const float* __restrict__ v_b1,  const float* __restrict__ v_w2,
    const float* __restrict__ v_b2,
    float* __restrict__ out)
{
    extern __shared__ char bp[];
    const int bid = blockIdx.x;
    const int t   = threadIdx.x;

    // =======================================================================
    // AUX: weight prep blocks (256..543)
    // =======================================================================
    if (bid >= 256 && bid < AUX_BLOCKS) {
        if (bid < 512) {                       // W2: transpose + scale + fp8
            int idx = (bid - 256) * 256 + t;
            int n = idx >> 7, k4 = (idx & 127) * 4;
            float w0 = ix_w2[(k4 + 0) * NH + n] * SCALE;
            float w1 = ix_w2[(k4 + 1) * NH + n] * SCALE;
            float w2v = ix_w2[(k4 + 2) * NH + n] * SCALE;
            float w3v = ix_w2[(k4 + 3) * NH + n] * SCALE;
            ((uint32_t*)g_w2f8)[n * 128 + (idx & 127)] = pack_e4m3x4(w0, w1, w2v, w3v);
        } else {                               // W3
            int idx = (bid - 512) * 256 + t;
            int n3 = idx >> 7, k4g = idx & 127;
            int k4 = k4g * 4;
            float w0 = ix_w3[(k4 + 0) * NBITS + n3] * SCALE;
            float w1 = ix_w3[(k4 + 1) * NBITS + n3] * SCALE;
            float w2v = ix_w3[(k4 + 2) * NBITS + n3] * SCALE;
            float w3v = ix_w3[(k4 + 3) * NBITS + n3] * SCALE;
            ((uint32_t*)g_w3f8)[n3 * 128 + k4g] = pack_e4m3x4(w0, w1, w2v, w3v);
        }
        __threadfence();
        __syncthreads();
        if (t == 0) atomicAdd(&g_sync[0], 1);
        return;
    }

    // =======================================================================
    // AUX: shift MLP blocks (0..255), FFMA2 row-pair packed, smem-aliased
    // =======================================================================
    if (bid < 256) {
        ull   (*xs2)[NBITS]  = (ull(*)[NBITS]) (bp + 0);
        ull   (*hs2)[NH]     = (ull(*)[NH])    (bp + 2048);
        ull   (*gs2)[NH]     = (ull(*)[NH])    (bp + 18432);
        float (*lgs)[NBITS]  = (float(*)[NBITS])(bp + 34816);
        float (*sms)[NBITS]  = (float(*)[NBITS])(bp + 36864);
        ull   (*sms2)[NBITS] = (ull(*)[NBITS]) (bp + 38912);

        const int b0 = bid * 8;
        const int c0 = 2 * t;

        {
            int p = t >> 6, k = t & 63;
            xs2[p][k] = packf2(shift_bits[(b0 + p) * NBITS + k],
                               shift_bits[(b0 + p + 4) * NBITS + k]);
        }
        __syncthreads();

        {   // layer 1
            ull a0[4], a1[4];
            #pragma unroll
            for (int p = 0; p < 4; p++) { a0[p] = 0; a1[p] = 0; }
            for (int k = 0; k < NBITS; k++) {
                float2 wv = ((const float2*)(sd_w1 + k * NH))[t];
                ull w0 = dupf(wv.x), w1 = dupf(wv.y);
                #pragma unroll
                for (int p = 0; p < 4; p++) {
                    ull x = xs2[p][k];
                    ffma2(a0[p], x, w0);
                    ffma2(a1[p], x, w1);
                }
            }
            float2 bv = ((const float2*)sd_b1)[t];
            #pragma unroll
            for (int p = 0; p < 4; p++) {
                float2 v0 = unpf2(a0[p]), v1 = unpf2(a1[p]);
                hs2[p][c0]     = packf2(fmaxf(v0.x + bv.x, 0.f), fmaxf(v0.y + bv.x, 0.f));
                hs2[p][c0 + 1] = packf2(fmaxf(v1.x + bv.y, 0.f), fmaxf(v1.y + bv.y, 0.f));
            }
        }
        __syncthreads();

        {   // layer 2
            ull a0[4], a1[4];
            #pragma unroll
            for (int p = 0; p < 4; p++) { a0[p] = 0; a1[p] = 0; }
            for (int k = 0; k < NH; k++) {
                float2 wv = ((const float2*)(sd_w2 + k * NH))[t];
                ull w0 = dupf(wv.x), w1 = dupf(wv.y);
                #pragma unroll
                for (int p = 0; p < 4; p++) {
                    ull h = hs2[p][k];
                    ffma2(a0[p], h, w0);
                    ffma2(a1[p], h, w1);
                }
            }
            float2 bv = ((const float2*)sd_b2)[t];
            #pragma unroll
            for (int p = 0; p < 4; p++) {
                float2 v0 = unpf2(a0[p]), v1 = unpf2(a1[p]);
                gs2[p][c0]     = packf2(fmaxf(v0.x + bv.x, 0.f), fmaxf(v0.y + bv.x, 0.f));
                gs2[p][c0 + 1] = packf2(fmaxf(v1.x + bv.y, 0.f), fmaxf(v1.y + bv.y, 0.f));
            }
        }
        __syncthreads();

        {   // layer 3
            int r = t >> 5, j = t & 31;
            const float* gview = (const float*)gs2;
            int lanesel = r >> 2, pp = r & 3;
            float acc0 = 0.f, acc1 = 0.f;
            for (int k = 0; k < NH; k++) {
                float gv = gview[(pp * NH + k) * 2 + lanesel];
                acc0 = fmaf(gv, sd_w3[k * NBITS + j],      acc0);
                acc1 = fmaf(gv, sd_w3[k * NBITS + j + 32], acc1);
            }
            lgs[r][j]      = acc0 + sd_b3[j];
            lgs[r][j + 32] = acc1 + sd_b3[j + 32];
        }
        __syncthreads();

        {   // softmax
            int wr = t >> 5, l = t & 31;
            float v0 = lgs[wr][l], v1 = lgs[wr][l + 32];
            float m = fmaxf(v0, v1);
            #pragma unroll
            for (int o = 16; o > 0; o >>= 1) m = fmaxf(m, __shfl_xor_sync(0xffffffffu, m, o));
            float e0 = expf(v0 - m), e1 = expf(v1 - m);
            float s = e0 + e1;
            #pragma unroll
            for (int o = 16; o > 0; o >>= 1) s += __shfl_xor_sync(0xffffffffu, s, o);
            float inv = 1.f / s;
            sms[wr][l] = e0 * inv;
            sms[wr][l + 32] = e1 * inv;
        }
        __syncthreads();
        {
            int p = t >> 6, k = t & 63;
            sms2[p][k] = packf2(sms[p][k], sms[p + 4][k]);
        }
        __syncthreads();

        {   // shift_part
            ull a0[4], a1[4];
            #pragma unroll
            for (int p = 0; p < 4; p++) { a0[p] = 0; a1[p] = 0; }
            for (int k = 0; k < NBITS; k++) {
                float2 wv = ((const float2*)(ix_w1 + (NBITS + k) * NH))[t];
                ull w0 = dupf(wv.x), w1 = dupf(wv.y);
                #pragma unroll
                for (int p = 0; p < 4; p++) {
                    ull s = sms2[p][k];
                    ffma2(a0[p], s, w0);
                    ffma2(a1[p], s, w1);
                }
            }
            #pragma unroll
            for (int p = 0; p < 4; p++) {
                float2 v0 = unpf2(a0[p]), v1 = unpf2(a1[p]);
                g_sp[(b0 + p) * NH + c0]         = v0.x;
                g_sp[(b0 + p + 4) * NH + c0]     = v0.y;
                g_sp[(b0 + p) * NH + c0 + 1]     = v1.x;
                g_sp[(b0 + p + 4) * NH + c0 + 1] = v1.y;
            }
        }

        if (t < 128) {   // v_shift
            ull a0[4], a1[4];
            #pragma unroll
            for (int p = 0; p < 4; p++) { a0[p] = 0; a1[p] = 0; }
            for (int k = 0; k < NBITS; k++) {
                float2 wv = ((const float2*)(v_w1 + (NBITS + k) * NHV))[t];
                ull w0 = dupf(wv.x), w1 = dupf(wv.y);
                #pragma unroll
                for (int p = 0; p < 4; p++) {
                    ull s = sms2[p][k];
                    ffma2(a0[p], s, w0);
                    ffma2(a1[p], s, w1);
                }
            }
            #pragma unroll
            for (int p = 0; p < 4; p++) {
                float2 v0 = unpf2(a0[p]), v1 = unpf2(a1[p]);
                g_vs[(b0 + p) * NHV + c0]         = v0.x;
                g_vs[(b0 + p + 4) * NHV + c0]     = v0.y;
                g_vs[(b0 + p) * NHV + c0 + 1]     = v1.x;
                g_vs[(b0 + p + 4) * NHV + c0 + 1] = v1.y;
            }
        }

        __threadfence();
        __syncthreads();
        if (t == 0) atomicExch(&g_sync[1 + bid], 1);
        return;
    }

    // =======================================================================
    // MAIN: FP8 mma chain, batch b = bid - 544, 2 CTAs/SM, double buffer.
    // =======================================================================
    const int b = bid - AUX_BLOCKS;

    float* b2s  = (float*)(bp + B2_OFF);
    float* b3s  = (float*)(bp + B3_OFF);
    float* ab_s = (float*)(bp + AB_OFF);
    float* vs_s = (float*)(bp + VS_OFF);
    float* vw2s = (float*)(bp + VW2_OFF);

    const int lane = t & 31, w = t >> 5;
    const int g = lane >> 2, tg = lane & 3;
    const int mg = w & 1, ng = w >> 1;       // 2m x 4n warp grid
    const uint32_t smb = smem_u32(bp);

    // independent staging (no aux deps)
    for (int i = t; i < NH; i += 256)
        b2s[i] = ix_b2[i] * SCALE;
    vw2s[t] = v_w2[t];
    if (t < NBITS) { b3s[t] = ix_b3[t]; ab_s[t] = a_bits[b * NBITS + t]; }

    // wait ONLY for this batch's shift block, then do real work (h1 build)
    if (t == 0) {
        volatile int* sy = g_sync;
        while (sy[1 + (b >> 3)] == 0) __nanosleep(100);
    }
    __syncthreads();
    __threadfence();

    vs_s[t] = g_vs[b * NHV + t] + v_b1[t];

    // h1 build: e4m3 (x16) [64 rows][512 k], stride 528 B
    #pragma unroll 4
    for (int i = 0; i < 32; i++) {
        int idx = t + i * 256;
        int mm = idx >> 7, qq = idx & 127;
        int k = qq * 4;
        float4 p  = *(const float4*)(ix_w1 + mm * NH + k);
        float4 s  = *(const float4*)(g_sp + b * NH + k);
        float4 bb = *(const float4*)(ix_b1 + k);
        float v0 = fmaxf(p.x + s.x + bb.x, 0.f) * SCALE;
        float v1 = fmaxf(p.y + s.y + bb.y, 0.f) * SCALE;
        float v2 = fmaxf(p.z + s.z + bb.z, 0.f) * SCALE;
        float v3 = fmaxf(p.w + s.w + bb.w, 0.f) * SCALE;
        *(uint32_t*)(bp + H1_OFF + mm * H1_STR + k) = pack_e4m3x4(v0, v1, v2, v3);
    }

    // now wait for weight preps, then start the W2 pipeline
    if (t == 0) {
        volatile int* sy = g_sync;
        while (sy[0] < 288) __nanosleep(200);
    }
    __syncthreads();
    __threadfence();

    {   // prologue: W2 chunk 0
        #pragma unroll
        for (int i = 0; i < 4; i++) {
            int idx = t + i * 256;
            int row = idx >> 3, c16 = idx & 7;
            cp16(smb + W2_OFF + row * W2_STR + c16 * 16,
                 g_w2f8 + row * NH + c16 * 16);
        }
        asm volatile("cp.async.commit_group;" ::: "memory");
    }

    float lg[2][2][4];
    #pragma unroll
    for (int mt = 0; mt < 2; mt++)
        #pragma unroll
        for (int nt = 0; nt < 2; nt++)
            #pragma unroll
            for (int j2 = 0; j2 < 4; j2++) lg[mt][nt][j2] = 0.f;

    float acc[2][4][4];

    const uint32_t bfrag = (uint32_t)((lane & 7) * W2_STR + (lane >> 3) * 16);
    uint32_t h1a[2];
    h1a[0] = smb + H1_OFF + (uint32_t)((mg * 32 + (lane & 15)) * H1_STR + (lane >> 4) * 16);
    h1a[1] = h1a[0] + 16 * H1_STR;
    const uint32_t w3b = smb + W3_OFF + (uint32_t)(ng * 16 * W2_STR) + bfrag;
    const uint32_t h2base = smb + H2_OFF;

    #pragma unroll
    for (int c = 0; c < 16; c++) {
        const int nb = c >> 2, kb = c & 3;
        const int next = c + 1;
        if (next < 16) {
            int nnb = next >> 2, nkb = next & 3;
            const uint8_t* src = g_w2f8 + (nnb * 128) * NH + nkb * 128;
            uint32_t dstb = smb + W2_OFF + (next & 1) * W2_TILE;
            #pragma unroll
            for (int i = 0; i < 4; i++) {
                int idx = t + i * 256;
                int row = idx >> 3, c16 = idx & 7;
                cp16(dstb + row * W2_STR + c16 * 16, src + row * NH + c16 * 16);
            }
            if (nkb == 1) {
                #pragma unroll
                for (int i = 0; i < 2; i++) {
                    int idx = t + i * 256;
                    int row = idx >> 3, c16 = idx & 7;
                    cp16(smb + W3_OFF + row * W2_STR + c16 * 16,
                         g_w3f8 + row * NH + nnb * 128 + c16 * 16);
                }
            }
            asm volatile("cp.async.commit_group;" ::: "memory");
            asm volatile("cp.async.wait_group 1;" ::: "memory");
        } else {
            asm volatile("cp.async.wait_group 0;" ::: "memory");
        }
        __syncthreads();

        if (kb == 0) {
            #pragma unroll
            for (int mt = 0; mt < 2; mt++)
                #pragma unroll
                for (int nt = 0; nt < 4; nt++) {
                    acc[mt][nt][0] = 0.f; acc[mt][nt][1] = 0.f;
                    acc[mt][nt][2] = 0.f; acc[mt][nt][3] = 0.f;
                }
        }

        const uint32_t bufA = smb + W2_OFF + (c & 1) * W2_TILE;
        const uint32_t w2b = bufA + (uint32_t)(ng * 32 * W2_STR) + bfrag;
        const uint32_t akb = (uint32_t)(kb * 128);

        #pragma unroll
        for (int ks2 = 0; ks2 < 2; ks2++) {
            uint32_t Bv[4][4];
            #pragma unroll
            for (int nt = 0; nt < 4; nt++)
                ldm_x4(Bv[nt], w2b + nt * (8 * W2_STR) + ks2 * 64);
            uint32_t Am[2][2][4];
            #pragma unroll
            for (int mt = 0; mt < 2; mt++) {
                ldm_x4(Am[mt][0], h1a[mt] + akb + (2 * ks2)     * 32);
                ldm_x4(Am[mt][1], h1a[mt] + akb + (2 * ks2 + 1) * 32);
            }
            #pragma unroll
            for (int mt = 0; mt < 2; mt++)
                #pragma unroll
                for (int nt = 0; nt < 4; nt++) {
                    mma_fp8(acc[mt][nt], Am[mt][0], Bv[nt][0], Bv[nt][1]);
                    mma_fp8(acc[mt][nt], Am[mt][1], Bv[nt][2], Bv[nt][3]);
                }
        }

        if (kb == 3) {
            // write h2 to DEDICATED buffer (no pre-sync needed: own acc only)
            #pragma unroll
            for (int mt = 0; mt < 2; mt++)
                #pragma unroll
                for (int nt = 0; nt < 4; nt++) {
                    int col = ng * 32 + nt * 8 + tg * 2;
                    float bb0 = b2s[nb * 128 + col], bb1 = b2s[nb * 128 + col + 1];
                    int r0 = mg * 32 + mt * 16 + g;
                    uint16_t p0 = pack_e4m3x2(
                        fmaxf(acc[mt][nt][0] * 0.0625f + bb0, 0.f),
                        fmaxf(acc[mt][nt][1] * 0.0625f + bb1, 0.f));
                    uint16_t p1 = pack_e4m3x2(
                        fmaxf(acc[mt][nt][2] * 0.0625f + bb0, 0.f),
                        fmaxf(acc[mt][nt][3] * 0.0625f + bb1, 0.f));
                    *(uint16_t*)(bp + H2_OFF + r0 * W2_STR + col) = p0;
                    *(uint16_t*)(bp + H2_OFF + (r0 + 8) * W2_STR + col) = p1;
                }
            __syncthreads();   // all h2 written before any warp reads it

            uint32_t a2b[2];
            a2b[0] = h2base + (uint32_t)((mg * 32 + (lane & 15)) * W2_STR + (lane >> 4) * 16);
            a2b[1] = a2b[0] + 16 * W2_STR;
            #pragma unroll
            for (int ks2 = 0; ks2 < 2; ks2++) {
                uint32_t B2v[2][4];
                #pragma unroll
                for (int nt = 0; nt < 2; nt++)
                    ldm_x4(B2v[nt], w3b + nt * (8 * W2_STR) + ks2 * 64);
                uint32_t A2[2][2][4];
                #pragma unroll
                for (int mt = 0; mt < 2; mt++) {
                    ldm_x4(A2[mt][0], a2b[mt] + (2 * ks2)     * 32);
                    ldm_x4(A2[mt][1], a2b[mt] + (2 * ks2 + 1) * 32);
                }
                #pragma unroll
                for (int mt = 0; mt < 2; mt++)
                    #pragma unroll
                    for (int nt = 0; nt < 2; nt++) {
                        mma_fp8(lg[mt][nt], A2[mt][0], B2v[nt][0], B2v[nt][1]);
                        mma_fp8(lg[mt][nt], A2[mt][1], B2v[nt][2], B2v[nt][3]);
                    }
            }
        }
        __syncthreads();
    }

    // logits -> smem (f32, stride 68), reusing W2 buffer 0
    float* lbuf = (float*)(bp + LG_OFF);
    #pragma unroll
    for (int mt = 0; mt < 2; mt++)
        #pragma unroll
        for (int nt = 0; nt < 2; nt++) {
            int col = ng * 16 + nt * 8 + tg * 2;
            int r0 = mg * 32 + mt * 16 + g;
            lbuf[r0 * 68 + col]     = lg[mt][nt][0];
            lbuf[r0 * 68 + col + 1] = lg[mt][nt][1];
            lbuf[(r0 + 8) * 68 + col]     = lg[mt][nt][2];
            lbuf[(r0 + 8) * 68 + col + 1] = lg[mt][nt][3];
        }
    __syncthreads();

    // epilogue: 4 threads per row (quad), 64 rows. lg = 256 x true logits.
    {
        const int row = t >> 2, tq = t & 3;
        float v[16];
        float mx = -1e30f;
        #pragma unroll
        for (int i = 0; i < 16; i++) {
            int col = i * 4 + tq;
            v[i] = lbuf[row * 68 + col] * INV_SC2 + b3s[col];
            mx = fmaxf(mx, v[i]);
        }
        mx = fmaxf(mx, __shfl_xor_sync(0xffffffffu, mx, 1));
        mx = fmaxf(mx, __shfl_xor_sync(0xffffffffu, mx, 2));

        float den = 0.f, num = 0.f;
        #pragma unroll
        for (int i = 0; i < 16; i++) {
            float e = expf(v[i] - mx);
            den += e;
            num = fmaf(e, ab_s[i * 4 + tq], num);
        }
        den += __shfl_xor_sync(0xffffffffu, den, 1);
        den += __shfl_xor_sync(0xffffffffu, den, 2);
        num += __shfl_xor_sync(0xffffffffu, num, 1);
        num += __shfl_xor_sync(0xffffffffu, num, 2);
        float pointed = num / den;

        // valid head: vectorized float4 loads (quad covers 16 j per step)
        const float* vrow = v_w1 + row * NHV;
        float acc2 = 0.f;
        #pragma unroll 4
        for (int jj = 0; jj < 16; jj++) {
            int j = jj * 16 + tq * 4;
            float4 vv = *(const float4*)(vrow + j);
            float4 vs = *(const float4*)(vs_s + j);
            float4 ww = *(const float4*)(vw2s + j);
            acc2 = fmaf(fmaxf(vv.x + vs.x, 0.f), ww.x, acc2);
            acc2 = fmaf(fmaxf(vv.y + vs.y, 0.f), ww.y, acc2);
            acc2 = fmaf(fmaxf(vv.z + vs.z, 0.f), ww.z, acc2);
            acc2 = fmaf(fmaxf(vv.w + vs.w, 0.f), ww.w, acc2);
        }
        acc2 += __shfl_xor_sync(0xffffffffu, acc2, 1);
        acc2 += __shfl_xor_sync(0xffffffffu, acc2, 2);
        if (tq == 0) {
            float vlog = acc2 + v_b2[0];
            out[b * NBITS + row] = pointed * (1.f / (1.f + expf(-vlog)));
        }
    }
}

extern "C" void kernel_launch(void* const* d_in, const int* in_sizes, int n_in,
                              void* d_out, int out_size)
{
    const float* a_bits     = (const float*)d_in[0];
    const float* shift_bits = (const float*)d_in[1];
    const float* sd_w1 = (const float*)d_in[2];
    const float* sd_b1 = (const float*)d_in[3];
    const float* sd_w2 = (const float*)d_in[4];
    const float* sd_b2 = (const float*)d_in[5];
    const float* sd_w3 = (const float*)d_in[6];
    const float* sd_b3 = (const float*)d_in[7];
    const float* ix_w1 = (const float*)d_in[8];
    const float* ix_b1 = (const float*)d_in[9];
    const float* ix_w2 = (const float*)d_in[10];
    const float* ix_b2 = (const float*)d_in[11];
    const float* ix_w3 = (const float*)d_in[12];
    const float* ix_b3 = (const float*)d_in[13];
    const float* v_w1  = (const float*)d_in[14];
    const float* v_b1  = (const float*)d_in[15];
    const float* v_w2  = (const float*)d_in[16];
    const float* v_b2  = (const float*)d_in[17];
    float* out = (float*)d_out;

    cudaFuncSetAttribute(fused_kernel,
                         cudaFuncAttributeMaxDynamicSharedMemorySize, SM_TOTAL);

    void* sync_ptr = nullptr;
    cudaGetSymbolAddress(&sync_ptr, g_sync);
    cudaMemsetAsync(sync_ptr, 0, sizeof(int) * 257);

    fused_kernel<<<AUX_BLOCKS + NB, 256, SM_TOTAL>>>(
        shift_bits, sd_w1, sd_b1, sd_w2, sd_b2, sd_w3, sd_b3,
        ix_w1, v_w1, ix_w2, ix_w3,
        a_bits, ix_b1, ix_b2, ix_b3, v_b1, v_w2, v_b2, out);
}